// round 8
// baseline (speedup 1.0000x reference)
#include <cuda_runtime.h>
#include <math.h>

#define BATCH 16
#define DIM   48
#define HID   16
#define CH    8
#define IMG   256
#define HW    (IMG*IMG)
#define ROWS  (BATCH*HW)

typedef unsigned long long u64;

__device__ float g_x1[(size_t)ROWS * CH];   // 33.5 MB
__device__ float g_n [(size_t)ROWS * CH];   // 33.5 MB

__device__ __forceinline__ u64 pk2(float a, float b) {
    u64 r;
    asm("mov.b64 %0,{%1,%2};" : "=l"(r) : "r"(__float_as_uint(a)), "r"(__float_as_uint(b)));
    return r;
}
__device__ __forceinline__ void upk2(u64 v, float& a, float& b) {
    unsigned lo, hi;
    asm("mov.b64 {%0,%1},%2;" : "=r"(lo), "=r"(hi) : "l"(v));
    a = __uint_as_float(lo); b = __uint_as_float(hi);
}
__device__ __forceinline__ void fma2(u64& d, u64 a, u64 b) {
    asm("fma.rn.f32x2 %0,%1,%2,%0;" : "+l"(d) : "l"(a), "l"(b));
}

// A&S 7.1.26 erf-based exact-form GELU (|abs err| ~1.5e-7, validated R3-R7)
__device__ __forceinline__ float gelu_f(float v) {
    float s = fabsf(v) * 0.7071067811865476f;
    float t = __fdividef(1.0f, fmaf(0.3275911f, s, 1.0f));
    float p = fmaf(1.061405429f, t, -1.453152027f);
    p = fmaf(p, t, 1.421413741f);
    p = fmaf(p, t, -0.284496736f);
    p = fmaf(p, t, 0.254829592f);
    p *= t;
    float e = fmaf(-p, __expf(-s * s), 1.0f);
    e = copysignf(e, v);
    return 0.5f * v * (1.0f + e);
}

// ---------------------------------------------------------------------------
// K1: smem-staged x tile (coalesced GMEM loads, conflict-free LDS reads),
// then per-thread packed-fma GEMM + gelu^2 + LN (R5's proven compute path).
// ---------------------------------------------------------------------------
#define K1T 128
#define XPAD 49   // 49 mod 32 = 17, coprime with 32 -> conflict-free row reads

__global__ __launch_bounds__(K1T, 6) void k1_gemm_gelu_ln(
    const float* __restrict__ x, const float* __restrict__ W1,
    const float* __restrict__ b1, const float* __restrict__ gamma,
    const float* __restrict__ beta)
{
    __shared__ float sxt[K1T * XPAD];            // 25.1 KB
    __shared__ __align__(16) float sW1[DIM * HID];
    __shared__ u64  sb1_2[HID / 2];
    __shared__ float sg[CH], sb[CH];

    int tid = threadIdx.x;
    for (int i = tid; i < DIM * HID; i += K1T) sW1[i] = W1[i];
    if (tid < HID / 2) sb1_2[tid] = pk2(b1[2 * tid], b1[2 * tid + 1]);
    if (tid < CH) { sg[tid] = gamma[tid]; sb[tid] = beta[tid]; }

    // Coalesced staging: warp reads 128B contiguous per instruction.
    // smem addr = (i/48)*49 + i%48 = i + i/48 (conflict-free store pattern).
    size_t base = (size_t)blockIdx.x * K1T * DIM;
    for (int i = tid; i < K1T * DIM; i += K1T)
        sxt[i + i / DIM] = x[base + i];
    __syncthreads();

    const float* xr = &sxt[tid * XPAD];

    u64 z2[8];
    #pragma unroll
    for (int q = 0; q < 8; q++) z2[q] = sb1_2[q];

    #pragma unroll
    for (int k4 = 0; k4 < DIM / 4; k4++) {
        float xs[4] = {xr[k4 * 4 + 0], xr[k4 * 4 + 1],
                       xr[k4 * 4 + 2], xr[k4 * 4 + 3]};
        #pragma unroll
        for (int kk = 0; kk < 4; kk++) {
            u64 xx = pk2(xs[kk], xs[kk]);
            const ulonglong2* wr = (const ulonglong2*)&sW1[(k4 * 4 + kk) * HID];
            #pragma unroll
            for (int q2 = 0; q2 < 4; q2++) {
                ulonglong2 w = wr[q2];
                fma2(z2[2 * q2],     xx, w.x);
                fma2(z2[2 * q2 + 1], xx, w.y);
            }
        }
    }

    float z[HID];
    #pragma unroll
    for (int q = 0; q < 8; q++) upk2(z2[q], z[2 * q], z[2 * q + 1]);

    #pragma unroll
    for (int j = 0; j < HID; j++) z[j] = gelu_f(gelu_f(z[j]));

    size_t r = (size_t)blockIdx.x * K1T + tid;
    float4* o1 = (float4*)(g_x1 + r * CH);
    o1[0] = make_float4(z[0], z[1], z[2], z[3]);
    o1[1] = make_float4(z[4], z[5], z[6], z[7]);

    float m = 0.f;
    #pragma unroll
    for (int j = 8; j < 16; j++) m += z[j];
    m *= 0.125f;
    float var = 0.f;
    #pragma unroll
    for (int j = 8; j < 16; j++) { float d = z[j] - m; var += d * d; }
    var *= 0.125f;
    float inv = rsqrtf(var + 1e-5f);

    float nn[CH];
    #pragma unroll
    for (int j = 0; j < CH; j++) nn[j] = (z[8 + j] - m) * inv * sg[j] + sb[j];

    float4* o2 = (float4*)(g_n + r * CH);
    o2[0] = make_float4(nn[0], nn[1], nn[2], nn[3]);
    o2[1] = make_float4(nn[4], nn[5], nn[6], nn[7]);
}

// ---------------------------------------------------------------------------
// K2: R6's best version verbatim (32x8 tile, 1 px/thread, padded scalar sn,
// all weight reads as LDS.128 broadcasts from transposed smem copies).
// ---------------------------------------------------------------------------
#define TX 32
#define TY 8
#define HALO_W (TX + 2)
#define HALO_H (TY + 2)
#define NPAD 9

__global__ __launch_bounds__(TX * TY, 3) void k2_conv_gate_gemm(
    const float* __restrict__ dw_w, const float* __restrict__ dw_b,
    const float* __restrict__ pw_w, const float* __restrict__ pw_b,
    const float* __restrict__ W2,   const float* __restrict__ b2,
    float* __restrict__ out)
{
    __shared__ float sn[HALO_H][HALO_W][NPAD];          // 12.3 KB
    __shared__ __align__(16) float sdwT[9 * CH];        // [tap][c]
    __shared__ __align__(16) float spwT[CH * CH];       // [cin][cout]
    __shared__ __align__(16) float sW2T[DIM * CH];      // [d][c]
    __shared__ float sdwb[CH], spwb[CH], sb2[DIM];

    int tid = threadIdx.y * TX + threadIdx.x;

    if (tid < 9 * CH) {
        int tap = tid / CH, c = tid % CH;
        sdwT[tid] = dw_w[c * 9 + tap];
    }
    if (tid >= 96 && tid < 160) {
        int i = tid - 96;
        int ci = i / CH, co = i % CH;
        spwT[i] = pw_w[co * CH + ci];
    }
    if (tid >= 160 && tid < 168) sdwb[tid - 160] = dw_b[tid - 160];
    if (tid >= 176 && tid < 184) spwb[tid - 176] = pw_b[tid - 176];
    if (tid >= 192 && tid < 240) sb2[tid - 192]  = b2[tid - 192];
    for (int i = tid; i < DIM * CH; i += TX * TY) {
        int d = i / CH, c = i % CH;
        sW2T[i] = W2[c * DIM + d];
    }

    int b   = blockIdx.z;
    int tx0 = blockIdx.x * TX;
    int ty0 = blockIdx.y * TY;
    const float* nb = g_n + (size_t)b * HW * CH;

    for (int i = tid; i < HALO_H * HALO_W; i += TX * TY) {
        int hy = i / HALO_W, hx = i % HALO_W;
        int gy = ty0 + hy - 1, gx = tx0 + hx - 1;
        float4 a = make_float4(0.f, 0.f, 0.f, 0.f);
        float4 c = make_float4(0.f, 0.f, 0.f, 0.f);
        if (gy >= 0 && gy < IMG && gx >= 0 && gx < IMG) {
            const float4* src = (const float4*)(nb + ((size_t)gy * IMG + gx) * CH);
            a = src[0]; c = src[1];
        }
        float* dst = &sn[hy][hx][0];
        dst[0] = a.x; dst[1] = a.y; dst[2] = a.z; dst[3] = a.w;
        dst[4] = c.x; dst[5] = c.y; dst[6] = c.z; dst[7] = c.w;
    }
    __syncthreads();

    const float4* sdwT4 = (const float4*)sdwT;
    const float4* spwT4 = (const float4*)spwT;
    const float4* sW2T4 = (const float4*)sW2T;

    int lx = threadIdx.x + 1, ly = threadIdx.y + 1;

    float ncen[CH];
    #pragma unroll
    for (int c = 0; c < CH; c++) ncen[c] = sn[ly][lx][c];

    float sp[CH];
    #pragma unroll
    for (int c = 0; c < CH; c++) sp[c] = sdwb[c];
    #pragma unroll
    for (int dy = 0; dy < 3; dy++) {
        #pragma unroll
        for (int dx = 0; dx < 3; dx++) {
            int tap = dy * 3 + dx;
            float4 wA = sdwT4[tap * 2];
            float4 wB = sdwT4[tap * 2 + 1];
            const float* nv = &sn[ly + dy - 1][lx + dx - 1][0];
            sp[0] += nv[0] * wA.x; sp[1] += nv[1] * wA.y;
            sp[2] += nv[2] * wA.z; sp[3] += nv[3] * wA.w;
            sp[4] += nv[4] * wB.x; sp[5] += nv[5] * wB.y;
            sp[6] += nv[6] * wB.z; sp[7] += nv[7] * wB.w;
        }
    }

    float chv[CH];
    #pragma unroll
    for (int c = 0; c < CH; c++) chv[c] = spwb[c];
    #pragma unroll
    for (int i = 0; i < CH; i++) {
        float v = ncen[i];
        float4 wA = spwT4[i * 2];
        float4 wB = spwT4[i * 2 + 1];
        chv[0] += v * wA.x; chv[1] += v * wA.y;
        chv[2] += v * wA.z; chv[3] += v * wA.w;
        chv[4] += v * wB.x; chv[5] += v * wB.y;
        chv[6] += v * wB.z; chv[7] += v * wB.w;
    }

    int p = (ty0 + threadIdx.y) * IMG + (tx0 + threadIdx.x);
    const float4* x1p = (const float4*)(g_x1 + ((size_t)b * HW + p) * CH);
    float4 xa = x1p[0], xb = x1p[1];
    float g[CH] = {xa.x, xa.y, xa.z, xa.w, xb.x, xb.y, xb.z, xb.w};
    #pragma unroll
    for (int c = 0; c < CH; c++) g[c] *= sp[c] * chv[c];

    float* ob = out + (size_t)b * DIM * HW + p;
    #pragma unroll
    for (int d = 0; d < DIM; d++) {
        float4 wA = sW2T4[d * 2], wB = sW2T4[d * 2 + 1];
        float acc = sb2[d];
        acc = fmaf(g[0], wA.x, acc); acc = fmaf(g[1], wA.y, acc);
        acc = fmaf(g[2], wA.z, acc); acc = fmaf(g[3], wA.w, acc);
        acc = fmaf(g[4], wB.x, acc); acc = fmaf(g[5], wB.y, acc);
        acc = fmaf(g[6], wB.z, acc); acc = fmaf(g[7], wB.w, acc);
        ob[(size_t)d * HW] = acc;
    }
}

extern "C" void kernel_launch(void* const* d_in, const int* in_sizes, int n_in,
                              void* d_out, int out_size)
{
    const float* x     = (const float*)d_in[0];
    const float* W1    = (const float*)d_in[1];
    const float* b1    = (const float*)d_in[2];
    const float* gamma = (const float*)d_in[3];
    const float* beta  = (const float*)d_in[4];
    const float* dw_w  = (const float*)d_in[5];
    const float* dw_b  = (const float*)d_in[6];
    const float* pw_w  = (const float*)d_in[7];
    const float* pw_b  = (const float*)d_in[8];
    const float* W2    = (const float*)d_in[9];
    const float* b2    = (const float*)d_in[10];
    float* out = (float*)d_out;

    k1_gemm_gelu_ln<<<ROWS / K1T, K1T>>>(x, W1, b1, gamma, beta);

    dim3 g2(IMG / TX, IMG / TY, BATCH);
    k2_conv_gate_gemm<<<g2, dim3(TX, TY)>>>(dw_w, dw_b, pw_w, pw_b, W2, b2, out);
}

// round 9
// speedup vs baseline: 1.3708x; 1.3708x over previous
#include <cuda_runtime.h>
#include <math.h>

#define BATCH 16
#define DIM   48
#define HID   16
#define CH    8
#define IMG   256
#define HW    (IMG*IMG)
#define ROWS  (BATCH*HW)

typedef unsigned long long u64;

__device__ float g_x1[(size_t)ROWS * CH];   // 33.5 MB
__device__ float g_n [(size_t)ROWS * CH];   // 33.5 MB

__device__ __forceinline__ u64 pk2(float a, float b) {
    u64 r;
    asm("mov.b64 %0,{%1,%2};" : "=l"(r) : "r"(__float_as_uint(a)), "r"(__float_as_uint(b)));
    return r;
}
__device__ __forceinline__ void upk2(u64 v, float& a, float& b) {
    unsigned lo, hi;
    asm("mov.b64 {%0,%1},%2;" : "=r"(lo), "=r"(hi) : "l"(v));
    a = __uint_as_float(lo); b = __uint_as_float(hi);
}
__device__ __forceinline__ void fma2(u64& d, u64 a, u64 b) {
    asm("fma.rn.f32x2 %0,%1,%2,%0;" : "+l"(d) : "l"(a), "l"(b));
}

// A&S 7.1.26 erf-based exact-form GELU (|abs err| ~1.5e-7, validated R3-R8)
__device__ __forceinline__ float gelu_f(float v) {
    float s = fabsf(v) * 0.7071067811865476f;
    float t = __fdividef(1.0f, fmaf(0.3275911f, s, 1.0f));
    float p = fmaf(1.061405429f, t, -1.453152027f);
    p = fmaf(p, t, 1.421413741f);
    p = fmaf(p, t, -0.284496736f);
    p = fmaf(p, t, 0.254829592f);
    p *= t;
    float e = fmaf(-p, __expf(-s * s), 1.0f);
    e = copysignf(e, v);
    return 0.5f * v * (1.0f + e);
}

// ---------------------------------------------------------------------------
// K1: R5's proven version (87 us). Packed f32x2 accumulators, direct LDG.128
// row reads, fast GELU, 64-reg cap via (256,4).
// ---------------------------------------------------------------------------
__global__ __launch_bounds__(256, 4) void k1_gemm_gelu_ln(
    const float* __restrict__ x, const float* __restrict__ W1,
    const float* __restrict__ b1, const float* __restrict__ gamma,
    const float* __restrict__ beta)
{
    __shared__ __align__(16) float sW1[DIM * HID];
    __shared__ u64  sb1_2[HID / 2];
    __shared__ float sg[CH], sb[CH];

    int tid = threadIdx.x;
    for (int i = tid; i < DIM * HID; i += 256) sW1[i] = W1[i];
    if (tid < HID / 2) sb1_2[tid] = pk2(b1[2 * tid], b1[2 * tid + 1]);
    if (tid < CH) { sg[tid] = gamma[tid]; sb[tid] = beta[tid]; }
    __syncthreads();

    int r = blockIdx.x * 256 + tid;
    const float4* xr = (const float4*)(x + (size_t)r * DIM);

    u64 z2[8];
    #pragma unroll
    for (int q = 0; q < 8; q++) z2[q] = sb1_2[q];

    #pragma unroll
    for (int k4 = 0; k4 < DIM / 4; k4++) {
        float4 v = xr[k4];
        float xs[4] = {v.x, v.y, v.z, v.w};
        #pragma unroll
        for (int kk = 0; kk < 4; kk++) {
            u64 xx = pk2(xs[kk], xs[kk]);
            const ulonglong2* wr = (const ulonglong2*)&sW1[(k4 * 4 + kk) * HID];
            #pragma unroll
            for (int q2 = 0; q2 < 4; q2++) {
                ulonglong2 w = wr[q2];
                fma2(z2[2 * q2],     xx, w.x);
                fma2(z2[2 * q2 + 1], xx, w.y);
            }
        }
    }

    float z[HID];
    #pragma unroll
    for (int q = 0; q < 8; q++) upk2(z2[q], z[2 * q], z[2 * q + 1]);

    #pragma unroll
    for (int j = 0; j < HID; j++) z[j] = gelu_f(gelu_f(z[j]));

    float4* o1 = (float4*)(g_x1 + (size_t)r * CH);
    o1[0] = make_float4(z[0], z[1], z[2], z[3]);
    o1[1] = make_float4(z[4], z[5], z[6], z[7]);

    float m = 0.f;
    #pragma unroll
    for (int j = 8; j < 16; j++) m += z[j];
    m *= 0.125f;
    float var = 0.f;
    #pragma unroll
    for (int j = 8; j < 16; j++) { float d = z[j] - m; var += d * d; }
    var *= 0.125f;
    float inv = rsqrtf(var + 1e-5f);

    float nn[CH];
    #pragma unroll
    for (int j = 0; j < CH; j++) nn[j] = (z[8 + j] - m) * inv * sg[j] + sb[j];

    float4* o2 = (float4*)(g_n + (size_t)r * CH);
    o2[0] = make_float4(nn[0], nn[1], nn[2], nn[3]);
    o2[1] = make_float4(nn[4], nn[5], nn[6], nn[7]);
}

// ---------------------------------------------------------------------------
// K2: 32x8 tile, 128 threads, 2 interleaved px/thread (tx, tx+16).
// Halo in float4 planes -> conv via conflict-free LDS.128 (18/px).
// Weight LDS.128 amortized over 2 px. Scalar FMA throughout (reg-safe).
// ---------------------------------------------------------------------------
#define TXW 32
#define TX2 16
#define TY 8
#define HAW (TXW + 2)
#define HAH (TY + 2)
#define NH  (HAW * HAH)     // 340
#define K2T (TX2 * TY)      // 128

__global__ __launch_bounds__(K2T, 6) void k2_conv_gate_gemm(
    const float* __restrict__ dw_w, const float* __restrict__ dw_b,
    const float* __restrict__ pw_w, const float* __restrict__ pw_b,
    const float* __restrict__ W2,   const float* __restrict__ b2,
    float* __restrict__ out)
{
    __shared__ float4 snA[NH], snB[NH];                 // 10.9 KB
    __shared__ __align__(16) float sdwT[9 * CH];        // [tap][c]
    __shared__ __align__(16) float spwT[CH * CH];       // [cin][cout]
    __shared__ __align__(16) float sW2T[DIM * CH];      // [d][c]
    __shared__ float sdwb[CH], spwb[CH], sb2[DIM];

    int tid = threadIdx.y * TX2 + threadIdx.x;

    if (tid < 9 * CH) {
        int tap = tid / CH, c = tid % CH;
        sdwT[tid] = dw_w[c * 9 + tap];
    }
    if (tid < CH * CH) {
        int ci = tid / CH, co = tid % CH;
        spwT[tid] = pw_w[co * CH + ci];
    }
    if (tid < CH)                  sdwb[tid] = dw_b[tid];
    if (tid >= 16 && tid < 24)     spwb[tid - 16] = pw_b[tid - 16];
    if (tid >= 32 && tid < 80)     sb2[tid - 32]  = b2[tid - 32];
    #pragma unroll
    for (int i = tid; i < DIM * CH; i += K2T) {
        int d = i / CH, c = i % CH;
        sW2T[i] = W2[c * DIM + d];
    }

    int b   = blockIdx.z;
    int tx0 = blockIdx.x * TXW;
    int ty0 = blockIdx.y * TY;
    const float* nb = g_n + (size_t)b * HW * CH;

    // Halo load into float4 planes (zero-pad = SAME)
    for (int i = tid; i < NH; i += K2T) {
        int hy = i / HAW, hx = i % HAW;
        int gy = ty0 + hy - 1, gx = tx0 + hx - 1;
        float4 a = make_float4(0.f, 0.f, 0.f, 0.f);
        float4 c = make_float4(0.f, 0.f, 0.f, 0.f);
        if (((unsigned)gy < IMG) & ((unsigned)gx < IMG)) {
            const float4* src = (const float4*)(nb + ((size_t)gy * IMG + gx) * CH);
            a = src[0]; c = src[1];
        }
        snA[i] = a; snB[i] = c;
    }
    __syncthreads();

    const float4* sdwT4 = (const float4*)sdwT;
    const float4* spwT4 = (const float4*)spwT;
    const float4* sW2T4 = (const float4*)sW2T;

    int ly = threadIdx.y + 1;
    int py = ty0 + threadIdx.y;

    float gA[CH], gB[CH];

    // ---- per-pixel conv + pw + gate (runs twice: px tx and tx+16) ----
    #pragma unroll
    for (int half = 0; half < 2; half++) {
        int lx = threadIdx.x + 1 + half * TX2;
        float* gout = half ? gB : gA;

        float sp[CH];
        #pragma unroll
        for (int c = 0; c < CH; c++) sp[c] = sdwb[c];
        float nc[CH];

        #pragma unroll
        for (int dy = 0; dy < 3; dy++) {
            #pragma unroll
            for (int dx = 0; dx < 3; dx++) {
                int tap = dy * 3 + dx;
                int idx = (ly + dy - 1) * HAW + (lx + dx - 1);
                float4 a  = snA[idx];
                float4 bv = snB[idx];
                float4 wA = sdwT4[tap * 2];
                float4 wB = sdwT4[tap * 2 + 1];
                sp[0] += a.x  * wA.x; sp[1] += a.y  * wA.y;
                sp[2] += a.z  * wA.z; sp[3] += a.w  * wA.w;
                sp[4] += bv.x * wB.x; sp[5] += bv.y * wB.y;
                sp[6] += bv.z * wB.z; sp[7] += bv.w * wB.w;
                if (tap == 4) {
                    nc[0] = a.x;  nc[1] = a.y;  nc[2] = a.z;  nc[3] = a.w;
                    nc[4] = bv.x; nc[5] = bv.y; nc[6] = bv.z; nc[7] = bv.w;
                }
            }
        }

        float chv[CH];
        #pragma unroll
        for (int c = 0; c < CH; c++) chv[c] = spwb[c];
        #pragma unroll
        for (int i = 0; i < CH; i++) {
            float v = nc[i];
            float4 wA = spwT4[i * 2];
            float4 wB = spwT4[i * 2 + 1];
            chv[0] += v * wA.x; chv[1] += v * wA.y;
            chv[2] += v * wA.z; chv[3] += v * wA.w;
            chv[4] += v * wB.x; chv[5] += v * wB.y;
            chv[6] += v * wB.z; chv[7] += v * wB.w;
        }

        int p = py * IMG + (tx0 + threadIdx.x + half * TX2);
        const float4* x1p = (const float4*)(g_x1 + ((size_t)b * HW + p) * CH);
        float4 xa = x1p[0], xb = x1p[1];
        gout[0] = xa.x * sp[0] * chv[0]; gout[1] = xa.y * sp[1] * chv[1];
        gout[2] = xa.z * sp[2] * chv[2]; gout[3] = xa.w * sp[3] * chv[3];
        gout[4] = xb.x * sp[4] * chv[4]; gout[5] = xb.y * sp[5] * chv[5];
        gout[6] = xb.z * sp[6] * chv[6]; gout[7] = xb.w * sp[7] * chv[7];
    }

    // ---- GEMM 8 -> 48 for both pixels; weight loads amortized x2 ----
    int p0 = py * IMG + tx0 + threadIdx.x;
    float* ob = out + (size_t)b * DIM * HW + p0;

    #pragma unroll
    for (int d = 0; d < DIM; d++) {
        float4 wA = sW2T4[d * 2], wB = sW2T4[d * 2 + 1];
        float bb = sb2[d];
        float a0 = bb, a1 = bb;
        a0 = fmaf(gA[0], wA.x, a0); a1 = fmaf(gB[0], wA.x, a1);
        a0 = fmaf(gA[1], wA.y, a0); a1 = fmaf(gB[1], wA.y, a1);
        a0 = fmaf(gA[2], wA.z, a0); a1 = fmaf(gB[2], wA.z, a1);
        a0 = fmaf(gA[3], wA.w, a0); a1 = fmaf(gB[3], wA.w, a1);
        a0 = fmaf(gA[4], wB.x, a0); a1 = fmaf(gB[4], wB.x, a1);
        a0 = fmaf(gA[5], wB.y, a0); a1 = fmaf(gB[5], wB.y, a1);
        a0 = fmaf(gA[6], wB.z, a0); a1 = fmaf(gB[6], wB.z, a1);
        a0 = fmaf(gA[7], wB.w, a0); a1 = fmaf(gB[7], wB.w, a1);
        size_t off = (size_t)d * HW;
        ob[off]       = a0;
        ob[off + TX2] = a1;
    }
}

extern "C" void kernel_launch(void* const* d_in, const int* in_sizes, int n_in,
                              void* d_out, int out_size)
{
    const float* x     = (const float*)d_in[0];
    const float* W1    = (const float*)d_in[1];
    const float* b1    = (const float*)d_in[2];
    const float* gamma = (const float*)d_in[3];
    const float* beta  = (const float*)d_in[4];
    const float* dw_w  = (const float*)d_in[5];
    const float* dw_b  = (const float*)d_in[6];
    const float* pw_w  = (const float*)d_in[7];
    const float* pw_b  = (const float*)d_in[8];
    const float* W2    = (const float*)d_in[9];
    const float* b2    = (const float*)d_in[10];
    float* out = (float*)d_out;

    k1_gemm_gelu_ln<<<ROWS / 256, 256>>>(x, W1, b1, gamma, beta);

    dim3 g2(IMG / TXW, IMG / TY, BATCH);
    k2_conv_gate_gemm<<<g2, dim3(TX2, TY)>>>(dw_w, dw_b, pw_w, pw_b, W2, b2, out);
}